// round 11
// baseline (speedup 1.0000x reference)
#include <cuda_runtime.h>
#include <math.h>
#include <stdint.h>

#define BB 2
#define TT 2048
#define CC 2048
#define HH 16
#define DD 128
#define NEGF -1000000000.0f

// Scratch (device globals — referenced ONLY from device code)
__device__ float g_qkv[(size_t)3 * BB * HH * TT * DD];  // [3][B][H][T][D]
__device__ float g_att[(size_t)BB * TT * CC];           // [B][T][C] (tf32-rounded)
__device__ float g_xc[(size_t)BB * TT * CC];            // x rounded to tf32
__device__ float g_wqc[(size_t)3 * CC * CC];            // Wqkv rounded
__device__ float g_woc[(size_t)CC * CC];                // Wout rounded
__device__ float g_cos[TT * 64];
__device__ float g_sin[TT * 64];

// ---------------------------------------------------------------------------
__device__ __forceinline__ uint32_t f2tf32(float x) {
    uint32_t r;
    asm volatile("cvt.rna.tf32.f32 %0, %1;\n" : "=r"(r) : "f"(x));
    return r;
}
__device__ __forceinline__ void cp_async16(void* smem, const void* gmem) {
    uint32_t s = (uint32_t)__cvta_generic_to_shared(smem);
    asm volatile("cp.async.cg.shared.global [%0], [%1], 16;\n" :: "r"(s), "l"(gmem));
}
__device__ __forceinline__ void mma_tf32(float4& d, const uint32_t a[4], const uint32_t b[2]) {
    asm volatile(
        "mma.sync.aligned.m16n8k8.row.col.f32.tf32.tf32.f32 "
        "{%0,%1,%2,%3}, {%4,%5,%6,%7}, {%8,%9}, {%0,%1,%2,%3};\n"
        : "+f"(d.x), "+f"(d.y), "+f"(d.z), "+f"(d.w)
        : "r"(a[0]), "r"(a[1]), "r"(a[2]), "r"(a[3]), "r"(b[0]), "r"(b[1]));
}

// ---------------------------------------------------------------------------
__global__ void rope_table_kernel() {
    int t = blockIdx.x;
    int d = threadIdx.x;  // 0..63
    double inv = exp2(-((double)(2 * d) / 128.0) * log2(10000.0));
    float f = (float)t * (float)inv;
    g_cos[t * 64 + d] = cosf(f);
    g_sin[t * 64 + d] = sinf(f);
}

// Round to tf32-valued fp32 into device-global dst (resolved in device code)
template <int WHICH>
__global__ void cvt_tf32_kernel(const float* __restrict__ src, int n4) {
    float* dst = (WHICH == 0) ? g_xc : (WHICH == 1) ? g_wqc : g_woc;
    int i = blockIdx.x * blockDim.x + threadIdx.x;
    if (i < n4) {
        float4 v = ((const float4*)src)[i];
        v.x = __uint_as_float(f2tf32(v.x));
        v.y = __uint_as_float(f2tf32(v.y));
        v.z = __uint_as_float(f2tf32(v.z));
        v.w = __uint_as_float(f2tf32(v.w));
        ((float4*)dst)[i] = v;
    }
}

// ---------------------------------------------------------------------------
// RoPE + rounding: q,k: rope + round to tf32; v: round. All in place.
// ---------------------------------------------------------------------------
__global__ void rope_split_kernel() {
    int idx = blockIdx.x;
    int t = idx & (TT - 1);
    int s = idx >> 11;
    float* p = g_qkv + ((size_t)s * TT + t) * DD;
    int d = threadIdx.x;

    if (s < 2 * BB * HH) {
        float cs = g_cos[t * 64 + d], sn = g_sin[t * 64 + d];
        float x1 = p[d], x2 = p[d + 64];
        p[d]      = __uint_as_float(f2tf32(x1 * cs - x2 * sn));
        p[d + 64] = __uint_as_float(f2tf32(x2 * cs + x1 * sn));
    } else {
        p[d]      = __uint_as_float(f2tf32(p[d]));
        p[d + 64] = __uint_as_float(f2tf32(p[d + 64]));
    }
}

// ---------------------------------------------------------------------------
// tf32 mma.sync GEMM (NT), 3-stage cp.async with R8 issue-before-wait
// ordering, dynamic smem (96 KB, 2 CTA/SM). BM=BN=128, BK=32, 256 threads.
// Both per-iter syncs retained (trailing sync protects buffer kt%3 from the
// next iteration's prefetch overwrite).
// EPI==0: A=g_xc, W=g_wqc, scatter into g_qkv.
// EPI==1: A=g_att, W=g_woc, plain row-major store to out.
// ---------------------------------------------------------------------------
#define GBK 32
#define STAGE_F (128 * GBK)
#define GEMM_SMEM (6 * STAGE_F * 4)   // 3 stages x (A+B) = 98304 B

__device__ __forceinline__ int sw_off(int row, int k) {
    return row * GBK + ((((k >> 2) ^ (row & 7)) << 2) | (k & 3));
}

template <int EPI>
__global__ void __launch_bounds__(256, 2) gemm_tf32(float* __restrict__ out) {
    extern __shared__ uint32_t gsm[];
    uint32_t* Abuf = gsm;                 // 3 * STAGE_F
    uint32_t* Bbuf = gsm + 3 * STAGE_F;   // 3 * STAGE_F

    const float* A = (EPI == 0) ? (const float*)g_xc  : (const float*)g_att;
    const float* W = (EPI == 0) ? (const float*)g_wqc : (const float*)g_woc;
    const int K = CC;
    const int N = (EPI == 0) ? 3 * CC : CC;

    const int tid = threadIdx.x;
    const int m0 = blockIdx.y * 128, n0 = blockIdx.x * 128;

    const int wid = tid >> 5;
    const int lane = tid & 31;
    const int wm = wid & 3;
    const int wn = wid >> 2;
    const int g = lane >> 2;
    const int c = lane & 3;

    const int lr = tid >> 3;
    const int lc4 = tid & 7;

    float4 acc[2][8];
#pragma unroll
    for (int i = 0; i < 2; i++)
#pragma unroll
        for (int j = 0; j < 8; j++) acc[i][j] = make_float4(0.f, 0.f, 0.f, 0.f);

    const int NT = K / GBK;

#define LOAD_STAGE(st, k0)                                                          \
    do {                                                                            \
        uint32_t* as_ = Abuf + (st) * STAGE_F;                                      \
        uint32_t* bs_ = Bbuf + (st) * STAGE_F;                                      \
        _Pragma("unroll")                                                           \
        for (int i_ = 0; i_ < 4; i_++) {                                            \
            int r_ = lr + i_ * 32;                                                  \
            int sw_ = (lc4 ^ (r_ & 7)) << 2;                                        \
            cp_async16(&as_[r_ * GBK + sw_], A + (size_t)(m0 + r_) * K + (k0) + lc4 * 4); \
            cp_async16(&bs_[r_ * GBK + sw_], W + (size_t)(n0 + r_) * K + (k0) + lc4 * 4); \
        }                                                                           \
    } while (0)

    // prologue: stages 0 and 1 in flight
    LOAD_STAGE(0, 0);
    asm volatile("cp.async.commit_group;\n");
    LOAD_STAGE(1, GBK);
    asm volatile("cp.async.commit_group;\n");

    for (int kt = 0; kt < NT; kt++) {
        // R8 ordering: issue the deepest prefetch BEFORE waiting
        if (kt + 2 < NT) {
            LOAD_STAGE((kt + 2) % 3, (kt + 2) * GBK);
        }
        asm volatile("cp.async.commit_group;\n");
        asm volatile("cp.async.wait_group 2;\n");   // stage kt landed
        __syncthreads();

        const uint32_t* as = Abuf + (kt % 3) * STAGE_F;
        const uint32_t* bs = Bbuf + (kt % 3) * STAGE_F;
#pragma unroll
        for (int ks = 0; ks < 4; ks++) {
            const int k0 = ks * 8;
            uint32_t ua[2][4], ub[8][2];
#pragma unroll
            for (int mf = 0; mf < 2; mf++) {
                int r0 = wm * 32 + mf * 16 + g;
                ua[mf][0] = as[sw_off(r0,     k0 + c)];
                ua[mf][1] = as[sw_off(r0 + 8, k0 + c)];
                ua[mf][2] = as[sw_off(r0,     k0 + c + 4)];
                ua[mf][3] = as[sw_off(r0 + 8, k0 + c + 4)];
            }
#pragma unroll
            for (int nf = 0; nf < 8; nf++) {
                int n = wn * 64 + nf * 8 + g;
                ub[nf][0] = bs[sw_off(n, k0 + c)];
                ub[nf][1] = bs[sw_off(n, k0 + c + 4)];
            }
#pragma unroll
            for (int mf = 0; mf < 2; mf++)
#pragma unroll
                for (int nf = 0; nf < 8; nf++) mma_tf32(acc[mf][nf], ua[mf], ub[nf]);
        }
        __syncthreads();   // all reads of stage kt done before it is overwritten
    }
#undef LOAD_STAGE

    if (EPI == 0) {
        const int which = n0 >> 11;
        const int hh = (n0 >> 7) & 15;
#pragma unroll
        for (int mf = 0; mf < 2; mf++) {
            int r0 = m0 + wm * 32 + mf * 16 + g;
            int b0i = r0 >> 11, t0 = r0 & 2047;
            int r1 = r0 + 8;
            int b1i = r1 >> 11, t1 = r1 & 2047;
            float* base0 = g_qkv + ((((size_t)which * BB + b0i) * HH + hh) * TT + t0) * DD;
            float* base1 = g_qkv + ((((size_t)which * BB + b1i) * HH + hh) * TT + t1) * DD;
#pragma unroll
            for (int nf = 0; nf < 8; nf++) {
                int col = wn * 64 + nf * 8 + 2 * c;
                *(float2*)(base0 + col) = make_float2(acc[mf][nf].x, acc[mf][nf].y);
                *(float2*)(base1 + col) = make_float2(acc[mf][nf].z, acc[mf][nf].w);
            }
        }
    } else {
#pragma unroll
        for (int mf = 0; mf < 2; mf++) {
            int r0 = m0 + wm * 32 + mf * 16 + g;
            int r1 = r0 + 8;
#pragma unroll
            for (int nf = 0; nf < 8; nf++) {
                int col = n0 + wn * 64 + nf * 8 + 2 * c;
                *(float2*)(out + (size_t)r0 * N + col) = make_float2(acc[mf][nf].x, acc[mf][nf].y);
                *(float2*)(out + (size_t)r1 * N + col) = make_float2(acc[mf][nf].z, acc[mf][nf].w);
            }
        }
    }
}

// ---------------------------------------------------------------------------
// Flash attention, tensor cores (R10 version, unchanged).
// K hi-only (1-pass S), Khi double-buffered, V single-buffered split waits.
// P rounded rna at store; PV single pass.
// ---------------------------------------------------------------------------
#define AM 128
#define AN 64
#define QST 132
#define KST 132
#define VST 136
#define PST 68

#define OFF_Q   0
#define OFF_KHI (AM * QST)                  // two K buffers
#define OFF_VHI (OFF_KHI + 2 * AN * KST)
#define OFF_P   (OFF_VHI + AN * VST)
#define ATTN_F  (OFF_P + AM * PST)          // 51200 floats
#define ATTN_SMEM (ATTN_F * 4)              // 204800 B

__global__ void __launch_bounds__(256, 1) attn_mma_kernel() {
    extern __shared__ float sm[];
    float* Qs = sm + OFF_Q;
    float* Khi[2] = { sm + OFF_KHI, sm + OFF_KHI + AN * KST };
    float* Vhi = sm + OFF_VHI;
    float* Ps  = sm + OFF_P;
    const uint32_t* uQs  = (const uint32_t*)Qs;
    const uint32_t* uVhi = (const uint32_t*)Vhi;
    const uint32_t* uPs  = (const uint32_t*)Ps;

    const int bh = blockIdx.y;
    const int b = bh >> 4;
    const int h = bh & 15;
    const int qt = (gridDim.x - 1) - blockIdx.x;   // heavy tiles first
    const int i0 = qt * AM;
    const float slope = (float)exp2(-0.5 * (double)(h + 1));
    const float scale = 0.08838834764831843f;      // 1/sqrt(128)

    const float* Qg = g_qkv + (size_t)bh * TT * DD;
    const float* Kg = g_qkv + ((size_t)(BB * HH) + bh) * TT * DD;
    const float* Vg = g_qkv + ((size_t)(2 * BB * HH) + bh) * TT * DD;

    const int tid = threadIdx.x;
    const int w = tid >> 5, lane = tid & 31;
    const int g = lane >> 2, c = lane & 3;
    const int r0 = w * 16;

    // prologue group: Q tile + K(0)
    for (int v = tid; v < AM * 32; v += 256) {
        int r = v >> 5, c4 = (v & 31) << 2;
        cp_async16(Qs + r * QST + c4, Qg + (size_t)(i0 + r) * DD + c4);
    }
    for (int v = tid; v < AN * 32; v += 256) {
        int r = v >> 5, c4 = (v & 31) << 2;
        cp_async16(Khi[0] + r * KST + c4, Kg + (size_t)r * DD + c4);
    }
    asm volatile("cp.async.commit_group;\n");

    float4 o[16];
#pragma unroll
    for (int i = 0; i < 16; i++) o[i] = make_float4(0.f, 0.f, 0.f, 0.f);
    float mr0 = -INFINITY, mr1 = -INFINITY, lr0 = 0.f, lr1 = 0.f;

    const int ntiles = 2 * (qt + 1);
    for (int kt = 0; kt < ntiles; kt++) {
        const int j0 = kt * AN;
        const int cur = kt & 1, nxt = cur ^ 1;

        __syncthreads();  // PV(kt-1) done (V free); S(kt-1) done (K[nxt] free)

        // issue V(kt)  [group]
        for (int v = tid; v < AN * 32; v += 256) {
            int r = v >> 5, c4 = (v & 31) << 2;
            cp_async16(Vhi + r * VST + c4, Vg + (size_t)(j0 + r) * DD + c4);
        }
        asm volatile("cp.async.commit_group;\n");

        // issue K(kt+1) prefetch into nxt  [group]
        if (kt + 1 < ntiles) {
            const int jn = (kt + 1) * AN;
            for (int v = tid; v < AN * 32; v += 256) {
                int r = v >> 5, c4 = (v & 31) << 2;
                cp_async16(Khi[nxt] + r * KST + c4, Kg + (size_t)(jn + r) * DD + c4);
            }
        }
        asm volatile("cp.async.commit_group;\n");

        // K(kt) (oldest pending) ready; V(kt) + K(kt+1) may still be in flight
        asm volatile("cp.async.wait_group 2;\n");
        __syncthreads();

        // ---- S = Qhi * Khi (single pass), 16 x 64 per warp ----
        const uint32_t* uKhi = (const uint32_t*)Khi[cur];
        float4 s[8];
#pragma unroll
        for (int nf = 0; nf < 8; nf++) s[nf] = make_float4(0.f, 0.f, 0.f, 0.f);
#pragma unroll 4
        for (int kc = 0; kc < 16; kc++) {
            const int k0 = kc * 8;
            uint32_t ua[4];
            ua[0] = uQs[(r0 + g)     * QST + k0 + c];
            ua[1] = uQs[(r0 + g + 8) * QST + k0 + c];
            ua[2] = uQs[(r0 + g)     * QST + k0 + c + 4];
            ua[3] = uQs[(r0 + g + 8) * QST + k0 + c + 4];
#pragma unroll
            for (int nf = 0; nf < 8; nf++) {
                uint32_t bhi[2];
                int nb = (nf * 8 + g) * KST + k0;
                bhi[0] = uKhi[nb + c]; bhi[1] = uKhi[nb + c + 4];
                mma_tf32(s[nf], ua, bhi);
            }
        }

        // ---- softmax (warp-local rows) ----
        const int ig0 = i0 + r0 + g;
        const int ig1 = ig0 + 8;
        float tm0 = -INFINITY, tm1 = -INFINITY;
#pragma unroll
        for (int nf = 0; nf < 8; nf++) {
            int jb = j0 + nf * 8 + 2 * c;
            s[nf].x = (jb     <= ig0) ? fmaf(slope, (float)(jb     - ig0), s[nf].x * scale) : NEGF;
            s[nf].y = (jb + 1 <= ig0) ? fmaf(slope, (float)(jb + 1 - ig0), s[nf].y * scale) : NEGF;
            s[nf].z = (jb     <= ig1) ? fmaf(slope, (float)(jb     - ig1), s[nf].z * scale) : NEGF;
            s[nf].w = (jb + 1 <= ig1) ? fmaf(slope, (float)(jb + 1 - ig1), s[nf].w * scale) : NEGF;
            tm0 = fmaxf(tm0, fmaxf(s[nf].x, s[nf].y));
            tm1 = fmaxf(tm1, fmaxf(s[nf].z, s[nf].w));
        }
        tm0 = fmaxf(tm0, __shfl_xor_sync(0xffffffffu, tm0, 1));
        tm0 = fmaxf(tm0, __shfl_xor_sync(0xffffffffu, tm0, 2));
        tm1 = fmaxf(tm1, __shfl_xor_sync(0xffffffffu, tm1, 1));
        tm1 = fmaxf(tm1, __shfl_xor_sync(0xffffffffu, tm1, 2));

        float mn0 = fmaxf(mr0, tm0), mn1 = fmaxf(mr1, tm1);
        float corr0 = __expf(mr0 - mn0), corr1 = __expf(mr1 - mn1);
        mr0 = mn0; mr1 = mn1;

        float rs0 = 0.f, rs1 = 0.f;
#pragma unroll
        for (int nf = 0; nf < 8; nf++) {
            // round P to tf32 (rna) at store; sum rounded values so the
            // normalization is self-consistent
            float p0 = __uint_as_float(f2tf32(__expf(s[nf].x - mn0)));
            float p1 = __uint_as_float(f2tf32(__expf(s[nf].y - mn0)));
            float p2 = __uint_as_float(f2tf32(__expf(s[nf].z - mn1)));
            float p3 = __uint_as_float(f2tf32(__expf(s[nf].w - mn1)));
            rs0 += p0 + p1;
            rs1 += p2 + p3;
            *(float2*)(Ps + (r0 + g)     * PST + nf * 8 + 2 * c) = make_float2(p0, p1);
            *(float2*)(Ps + (r0 + g + 8) * PST + nf * 8 + 2 * c) = make_float2(p2, p3);
        }
        rs0 += __shfl_xor_sync(0xffffffffu, rs0, 1);
        rs0 += __shfl_xor_sync(0xffffffffu, rs0, 2);
        rs1 += __shfl_xor_sync(0xffffffffu, rs1, 1);
        rs1 += __shfl_xor_sync(0xffffffffu, rs1, 2);
        lr0 = lr0 * corr0 + rs0;
        lr1 = lr1 * corr1 + rs1;
#pragma unroll
        for (int nf = 0; nf < 16; nf++) {
            o[nf].x *= corr0; o[nf].y *= corr0;
            o[nf].z *= corr1; o[nf].w *= corr1;
        }

        // V(kt) ready (only K(kt+1) may remain pending)
        asm volatile("cp.async.wait_group 1;\n");
        __syncthreads();

        // ---- O += P * Vhi (single pass), 16 x 128 per warp ----
#pragma unroll 2
        for (int kc = 0; kc < 8; kc++) {
            const int k0 = kc * 8;
            uint32_t ua[4];
            ua[0] = uPs[(r0 + g)     * PST + k0 + c];
            ua[1] = uPs[(r0 + g + 8) * PST + k0 + c];
            ua[2] = uPs[(r0 + g)     * PST + k0 + c + 4];
            ua[3] = uPs[(r0 + g + 8) * PST + k0 + c + 4];
#pragma unroll
            for (int nf = 0; nf < 16; nf++) {
                uint32_t bhi[2];
                bhi[0] = uVhi[(k0 + c)     * VST + nf * 8 + g];
                bhi[1] = uVhi[(k0 + c + 4) * VST + nf * 8 + g];
                mma_tf32(o[nf], ua, bhi);
            }
        }
    }

    // ---- epilogue ----
    float inv0 = 1.f / lr0, inv1 = 1.f / lr1;
    int t0 = i0 + r0 + g, t1 = t0 + 8;
    float* d0 = g_att + ((size_t)b * TT + t0) * CC + h * DD;
    float* d1 = g_att + ((size_t)b * TT + t1) * CC + h * DD;
#pragma unroll
    for (int nf = 0; nf < 16; nf++) {
        int col = nf * 8 + 2 * c;
        *(float2*)(d0 + col) = make_float2(__uint_as_float(f2tf32(o[nf].x * inv0)),
                                           __uint_as_float(f2tf32(o[nf].y * inv0)));
        *(float2*)(d1 + col) = make_float2(__uint_as_float(f2tf32(o[nf].z * inv1)),
                                           __uint_as_float(f2tf32(o[nf].w * inv1)));
    }
}

// ---------------------------------------------------------------------------
extern "C" void kernel_launch(void* const* d_in, const int* in_sizes, int n_in,
                              void* d_out, int out_size) {
    (void)in_sizes; (void)n_in; (void)out_size;
    const float* x    = (const float*)d_in[0];
    const float* Wqkv = (const float*)d_in[3];
    const float* Wout = (const float*)d_in[4];
    float* out = (float*)d_out;

    rope_table_kernel<<<TT, 64>>>();

    {
        int n4x = BB * TT * CC / 4;
        int n4q = 3 * CC * CC / 4;
        int n4o = CC * CC / 4;
        cvt_tf32_kernel<0><<<(n4x + 255) / 256, 256>>>(x, n4x);
        cvt_tf32_kernel<1><<<(n4q + 255) / 256, 256>>>(Wqkv, n4q);
        cvt_tf32_kernel<2><<<(n4o + 255) / 256, 256>>>(Wout, n4o);
    }

    cudaFuncSetAttribute(gemm_tf32<0>,
                         cudaFuncAttributeMaxDynamicSharedMemorySize, GEMM_SMEM);
    cudaFuncSetAttribute(gemm_tf32<1>,
                         cudaFuncAttributeMaxDynamicSharedMemorySize, GEMM_SMEM);

    dim3 g1(3 * CC / 128, BB * TT / 128);   // (48, 32)
    gemm_tf32<0><<<g1, 256, GEMM_SMEM>>>(nullptr);

    rope_split_kernel<<<3 * BB * HH * TT, 64>>>();

    cudaFuncSetAttribute(attn_mma_kernel,
                         cudaFuncAttributeMaxDynamicSharedMemorySize, ATTN_SMEM);
    dim3 g2(TT / AM, BB * HH);              // (16, 32)
    attn_mma_kernel<<<g2, 256, ATTN_SMEM>>>();

    dim3 g3(CC / 128, BB * TT / 128);       // (16, 32)
    gemm_tf32<1><<<g3, 256, GEMM_SMEM>>>(out);
}

// round 12
// speedup vs baseline: 1.2517x; 1.2517x over previous
#include <cuda_runtime.h>
#include <math.h>
#include <stdint.h>

#define BB 2
#define TT 2048
#define CC 2048
#define HH 16
#define DD 128
#define NEGF -1000000000.0f

// Scratch (device globals — referenced ONLY from device code)
__device__ float g_qkv[(size_t)3 * BB * HH * TT * DD];  // [3][B][H][T][D]
__device__ float g_att[(size_t)BB * TT * CC];           // [B][T][C] (tf32-rounded)
__device__ float g_xc[(size_t)BB * TT * CC];            // x rounded to tf32
__device__ float g_wqc[(size_t)3 * CC * CC];            // Wqkv rounded
__device__ float g_woc[(size_t)CC * CC];                // Wout rounded
__device__ float g_cos[TT * 64];
__device__ float g_sin[TT * 64];

// ---------------------------------------------------------------------------
__device__ __forceinline__ uint32_t f2tf32(float x) {
    uint32_t r;
    asm volatile("cvt.rna.tf32.f32 %0, %1;\n" : "=r"(r) : "f"(x));
    return r;
}
__device__ __forceinline__ void cp_async16(void* smem, const void* gmem) {
    uint32_t s = (uint32_t)__cvta_generic_to_shared(smem);
    asm volatile("cp.async.cg.shared.global [%0], [%1], 16;\n" :: "r"(s), "l"(gmem));
}
__device__ __forceinline__ void mma_tf32(float4& d, const uint32_t a[4], const uint32_t b[2]) {
    asm volatile(
        "mma.sync.aligned.m16n8k8.row.col.f32.tf32.tf32.f32 "
        "{%0,%1,%2,%3}, {%4,%5,%6,%7}, {%8,%9}, {%0,%1,%2,%3};\n"
        : "+f"(d.x), "+f"(d.y), "+f"(d.z), "+f"(d.w)
        : "r"(a[0]), "r"(a[1]), "r"(a[2]), "r"(a[3]), "r"(b[0]), "r"(b[1]));
}

// ---------------------------------------------------------------------------
__global__ void rope_table_kernel() {   // 256 threads, 4 positions/block
    int t = blockIdx.x * 4 + (threadIdx.x >> 6);
    int d = threadIdx.x & 63;
    double inv = exp2(-((double)(2 * d) / 128.0) * log2(10000.0));
    float f = (float)t * (float)inv;
    g_cos[t * 64 + d] = cosf(f);
    g_sin[t * 64 + d] = sinf(f);
}

// Round to tf32-valued fp32 into device-global dst (resolved in device code)
template <int WHICH>
__global__ void cvt_tf32_kernel(const float* __restrict__ src, int n4) {
    float* dst = (WHICH == 0) ? g_xc : (WHICH == 1) ? g_wqc : g_woc;
    int i = blockIdx.x * blockDim.x + threadIdx.x;
    if (i < n4) {
        float4 v = ((const float4*)src)[i];
        v.x = __uint_as_float(f2tf32(v.x));
        v.y = __uint_as_float(f2tf32(v.y));
        v.z = __uint_as_float(f2tf32(v.z));
        v.w = __uint_as_float(f2tf32(v.w));
        ((float4*)dst)[i] = v;
    }
}

// ---------------------------------------------------------------------------
// RoPE + rounding: q,k: rope + round to tf32; v: round. In place.
// 256 threads, 4 rows per block.
// ---------------------------------------------------------------------------
__global__ void rope_split_kernel() {
    int row = blockIdx.x * 4 + (threadIdx.x >> 6);
    int t = row & (TT - 1);
    int s = row >> 11;
    float* p = g_qkv + ((size_t)s * TT + t) * DD;
    int d = threadIdx.x & 63;

    if (s < 2 * BB * HH) {
        float cs = g_cos[t * 64 + d], sn = g_sin[t * 64 + d];
        float x1 = p[d], x2 = p[d + 64];
        p[d]      = __uint_as_float(f2tf32(x1 * cs - x2 * sn));
        p[d + 64] = __uint_as_float(f2tf32(x2 * cs + x1 * sn));
    } else {
        p[d]      = __uint_as_float(f2tf32(p[d]));
        p[d + 64] = __uint_as_float(f2tf32(p[d + 64]));
    }
}

// ---------------------------------------------------------------------------
// tf32 mma.sync GEMM (NT), 2-stage cp.async, static 64KB smem (R10-proven,
// untouched).
// ---------------------------------------------------------------------------
#define GBK 32
#define STAGE_F (128 * GBK)

__device__ __forceinline__ int sw_off(int row, int k) {
    return row * GBK + ((((k >> 2) ^ (row & 7)) << 2) | (k & 3));
}

template <int EPI>
__global__ void __launch_bounds__(256, 2) gemm_tf32(float* __restrict__ out) {
    __shared__ uint32_t As[2][STAGE_F];
    __shared__ uint32_t Bs[2][STAGE_F];

    const float* A = (EPI == 0) ? (const float*)g_xc  : (const float*)g_att;
    const float* W = (EPI == 0) ? (const float*)g_wqc : (const float*)g_woc;
    const int K = CC;
    const int N = (EPI == 0) ? 3 * CC : CC;

    const int tid = threadIdx.x;
    const int m0 = blockIdx.y * 128, n0 = blockIdx.x * 128;

    const int wid = tid >> 5;
    const int lane = tid & 31;
    const int wm = wid & 3;
    const int wn = wid >> 2;
    const int g = lane >> 2;
    const int c = lane & 3;

    const int lr = tid >> 3;
    const int lc4 = tid & 7;

    float4 acc[2][8];
#pragma unroll
    for (int i = 0; i < 2; i++)
#pragma unroll
        for (int j = 0; j < 8; j++) acc[i][j] = make_float4(0.f, 0.f, 0.f, 0.f);

    const int NT = K / GBK;

    {
#pragma unroll
        for (int i = 0; i < 4; i++) {
            int r = lr + i * 32;
            int sw = (lc4 ^ (r & 7)) << 2;
            cp_async16(&As[0][r * GBK + sw], A + (size_t)(m0 + r) * K + lc4 * 4);
            cp_async16(&Bs[0][r * GBK + sw], W + (size_t)(n0 + r) * K + lc4 * 4);
        }
        asm volatile("cp.async.commit_group;\n");
    }

    for (int kt = 0; kt < NT; kt++) {
        int cur = kt & 1;
        if (kt + 1 < NT) {
            int nxt = cur ^ 1;
            int k0 = (kt + 1) * GBK;
#pragma unroll
            for (int i = 0; i < 4; i++) {
                int r = lr + i * 32;
                int sw = (lc4 ^ (r & 7)) << 2;
                cp_async16(&As[nxt][r * GBK + sw], A + (size_t)(m0 + r) * K + k0 + lc4 * 4);
                cp_async16(&Bs[nxt][r * GBK + sw], W + (size_t)(n0 + r) * K + k0 + lc4 * 4);
            }
        }
        asm volatile("cp.async.commit_group;\n");
        asm volatile("cp.async.wait_group 1;\n");
        __syncthreads();

        const uint32_t* as = As[cur];
        const uint32_t* bs = Bs[cur];
#pragma unroll
        for (int ks = 0; ks < 4; ks++) {
            const int k0 = ks * 8;
            uint32_t ua[2][4], ub[8][2];
#pragma unroll
            for (int mf = 0; mf < 2; mf++) {
                int r0 = wm * 32 + mf * 16 + g;
                ua[mf][0] = as[sw_off(r0,     k0 + c)];
                ua[mf][1] = as[sw_off(r0 + 8, k0 + c)];
                ua[mf][2] = as[sw_off(r0,     k0 + c + 4)];
                ua[mf][3] = as[sw_off(r0 + 8, k0 + c + 4)];
            }
#pragma unroll
            for (int nf = 0; nf < 8; nf++) {
                int n = wn * 64 + nf * 8 + g;
                ub[nf][0] = bs[sw_off(n, k0 + c)];
                ub[nf][1] = bs[sw_off(n, k0 + c + 4)];
            }
#pragma unroll
            for (int mf = 0; mf < 2; mf++)
#pragma unroll
                for (int nf = 0; nf < 8; nf++) mma_tf32(acc[mf][nf], ua[mf], ub[nf]);
        }
        __syncthreads();
    }

    if (EPI == 0) {
        const int which = n0 >> 11;
        const int hh = (n0 >> 7) & 15;
#pragma unroll
        for (int mf = 0; mf < 2; mf++) {
            int r0 = m0 + wm * 32 + mf * 16 + g;
            int b0i = r0 >> 11, t0 = r0 & 2047;
            int r1 = r0 + 8;
            int b1i = r1 >> 11, t1 = r1 & 2047;
            float* base0 = g_qkv + ((((size_t)which * BB + b0i) * HH + hh) * TT + t0) * DD;
            float* base1 = g_qkv + ((((size_t)which * BB + b1i) * HH + hh) * TT + t1) * DD;
#pragma unroll
            for (int nf = 0; nf < 8; nf++) {
                int col = wn * 64 + nf * 8 + 2 * c;
                *(float2*)(base0 + col) = make_float2(acc[mf][nf].x, acc[mf][nf].y);
                *(float2*)(base1 + col) = make_float2(acc[mf][nf].z, acc[mf][nf].w);
            }
        }
    } else {
#pragma unroll
        for (int mf = 0; mf < 2; mf++) {
            int r0 = m0 + wm * 32 + mf * 16 + g;
            int r1 = r0 + 8;
#pragma unroll
            for (int nf = 0; nf < 8; nf++) {
                int col = n0 + wn * 64 + nf * 8 + 2 * c;
                *(float2*)(out + (size_t)r0 * N + col) = make_float2(acc[mf][nf].x, acc[mf][nf].y);
                *(float2*)(out + (size_t)r1 * N + col) = make_float2(acc[mf][nf].z, acc[mf][nf].w);
            }
        }
    }
}

// ---------------------------------------------------------------------------
// Flash attention, tensor cores. Key-tiles processed DESCENDING from the
// diagonal; ALiBi locality break (log-margin 40) skips far tiles; causal
// mask only on the two diagonal tiles; warp-uniform rescale skip.
// K hi-only (1-pass S), Khi double-buffered, V single-buffered split waits.
// P rounded rna at store; PV single pass.
// ---------------------------------------------------------------------------
#define AM 128
#define AN 64
#define QST 132
#define KST 132
#define VST 136
#define PST 68

#define OFF_Q   0
#define OFF_KHI (AM * QST)                  // two K buffers
#define OFF_VHI (OFF_KHI + 2 * AN * KST)
#define OFF_P   (OFF_VHI + AN * VST)
#define ATTN_F  (OFF_P + AM * PST)          // 51200 floats
#define ATTN_SMEM (ATTN_F * 4)              // 204800 B

__global__ void __launch_bounds__(256, 1) attn_mma_kernel() {
    extern __shared__ float sm[];
    float* Qs = sm + OFF_Q;
    float* Khi[2] = { sm + OFF_KHI, sm + OFF_KHI + AN * KST };
    float* Vhi = sm + OFF_VHI;
    float* Ps  = sm + OFF_P;
    const uint32_t* uQs  = (const uint32_t*)Qs;
    const uint32_t* uVhi = (const uint32_t*)Vhi;
    const uint32_t* uPs  = (const uint32_t*)Ps;

    const int bh = blockIdx.y;
    const int b = bh >> 4;
    const int h = bh & 15;
    const int qt = (gridDim.x - 1) - blockIdx.x;   // heavy tiles first
    const int i0 = qt * AM;
    const float slope = (float)exp2(-0.5 * (double)(h + 1));
    const float scale = 0.08838834764831843f;      // 1/sqrt(128)

    const float* Qg = g_qkv + (size_t)bh * TT * DD;
    const float* Kg = g_qkv + ((size_t)(BB * HH) + bh) * TT * DD;
    const float* Vg = g_qkv + ((size_t)(2 * BB * HH) + bh) * TT * DD;

    const int tid = threadIdx.x;
    const int w = tid >> 5, lane = tid & 31;
    const int g = lane >> 2, c = lane & 3;
    const int r0 = w * 16;

    const int ntiles = 2 * (qt + 1);

    // prologue group: Q tile + K(ntiles-1)  (start at the diagonal)
    for (int v = tid; v < AM * 32; v += 256) {
        int r = v >> 5, c4 = (v & 31) << 2;
        cp_async16(Qs + r * QST + c4, Qg + (size_t)(i0 + r) * DD + c4);
    }
    {
        const int j0 = (ntiles - 1) * AN;
        for (int v = tid; v < AN * 32; v += 256) {
            int r = v >> 5, c4 = (v & 31) << 2;
            cp_async16(Khi[0] + r * KST + c4, Kg + (size_t)(j0 + r) * DD + c4);
        }
    }
    asm volatile("cp.async.commit_group;\n");

    float4 o[16];
#pragma unroll
    for (int i = 0; i < 16; i++) o[i] = make_float4(0.f, 0.f, 0.f, 0.f);
    float mr0 = -INFINITY, mr1 = -INFINITY, lr0 = 0.f, lr1 = 0.f;

    for (int it = 0; it < ntiles; it++) {
        const int kt2 = ntiles - 1 - it;       // descending from diagonal
        const int j0 = kt2 * AN;
        const int cur = it & 1, nxt = cur ^ 1;

        // ALiBi locality: is the NEXT tile (kt2-1) beyond the horizon?
        const bool last = (kt2 == 0) ||
            (slope * (float)(i0 - (kt2 - 1) * AN - 63) > 40.0f);

        __syncthreads();  // PV(prev) done (V free); S(prev) done (K[nxt] free)

        // issue V(kt2)  [group]
        for (int v = tid; v < AN * 32; v += 256) {
            int r = v >> 5, c4 = (v & 31) << 2;
            cp_async16(Vhi + r * VST + c4, Vg + (size_t)(j0 + r) * DD + c4);
        }
        asm volatile("cp.async.commit_group;\n");

        // issue K(kt2-1) prefetch into nxt  [group]
        if (!last) {
            const int jn = (kt2 - 1) * AN;
            for (int v = tid; v < AN * 32; v += 256) {
                int r = v >> 5, c4 = (v & 31) << 2;
                cp_async16(Khi[nxt] + r * KST + c4, Kg + (size_t)(jn + r) * DD + c4);
            }
        }
        asm volatile("cp.async.commit_group;\n");

        // K(kt2) (oldest pending) ready
        asm volatile("cp.async.wait_group 2;\n");
        __syncthreads();

        // ---- S = Qhi * Khi (single pass), 16 x 64 per warp ----
        const uint32_t* uKhi = (const uint32_t*)Khi[cur];
        float4 s[8];
#pragma unroll
        for (int nf = 0; nf < 8; nf++) s[nf] = make_float4(0.f, 0.f, 0.f, 0.f);
#pragma unroll 4
        for (int kc = 0; kc < 16; kc++) {
            const int k0 = kc * 8;
            uint32_t ua[4];
            ua[0] = uQs[(r0 + g)     * QST + k0 + c];
            ua[1] = uQs[(r0 + g + 8) * QST + k0 + c];
            ua[2] = uQs[(r0 + g)     * QST + k0 + c + 4];
            ua[3] = uQs[(r0 + g + 8) * QST + k0 + c + 4];
#pragma unroll
            for (int nf = 0; nf < 8; nf++) {
                uint32_t bhi[2];
                int nb = (nf * 8 + g) * KST + k0;
                bhi[0] = uKhi[nb + c]; bhi[1] = uKhi[nb + c + 4];
                mma_tf32(s[nf], ua, bhi);
            }
        }

        // ---- scale + ALiBi (+causal mask only on diagonal tiles) ----
        const int ig0 = i0 + r0 + g;
        const int ig1 = ig0 + 8;
        const bool needmask = (kt2 >= ntiles - 2);
        float tm0 = -INFINITY, tm1 = -INFINITY;
#pragma unroll
        for (int nf = 0; nf < 8; nf++) {
            int jb = j0 + nf * 8 + 2 * c;
            if (needmask) {
                s[nf].x = (jb     <= ig0) ? fmaf(slope, (float)(jb     - ig0), s[nf].x * scale) : NEGF;
                s[nf].y = (jb + 1 <= ig0) ? fmaf(slope, (float)(jb + 1 - ig0), s[nf].y * scale) : NEGF;
                s[nf].z = (jb     <= ig1) ? fmaf(slope, (float)(jb     - ig1), s[nf].z * scale) : NEGF;
                s[nf].w = (jb + 1 <= ig1) ? fmaf(slope, (float)(jb + 1 - ig1), s[nf].w * scale) : NEGF;
            } else {
                s[nf].x = fmaf(slope, (float)(jb     - ig0), s[nf].x * scale);
                s[nf].y = fmaf(slope, (float)(jb + 1 - ig0), s[nf].y * scale);
                s[nf].z = fmaf(slope, (float)(jb     - ig1), s[nf].z * scale);
                s[nf].w = fmaf(slope, (float)(jb + 1 - ig1), s[nf].w * scale);
            }
            tm0 = fmaxf(tm0, fmaxf(s[nf].x, s[nf].y));
            tm1 = fmaxf(tm1, fmaxf(s[nf].z, s[nf].w));
        }
        tm0 = fmaxf(tm0, __shfl_xor_sync(0xffffffffu, tm0, 1));
        tm0 = fmaxf(tm0, __shfl_xor_sync(0xffffffffu, tm0, 2));
        tm1 = fmaxf(tm1, __shfl_xor_sync(0xffffffffu, tm1, 1));
        tm1 = fmaxf(tm1, __shfl_xor_sync(0xffffffffu, tm1, 2));

        float mn0 = fmaxf(mr0, tm0), mn1 = fmaxf(mr1, tm1);
        float corr0 = __expf(mr0 - mn0), corr1 = __expf(mr1 - mn1);
        mr0 = mn0; mr1 = mn1;

        float rs0 = 0.f, rs1 = 0.f;
#pragma unroll
        for (int nf = 0; nf < 8; nf++) {
            float p0 = __uint_as_float(f2tf32(__expf(s[nf].x - mn0)));
            float p1 = __uint_as_float(f2tf32(__expf(s[nf].y - mn0)));
            float p2 = __uint_as_float(f2tf32(__expf(s[nf].z - mn1)));
            float p3 = __uint_as_float(f2tf32(__expf(s[nf].w - mn1)));
            rs0 += p0 + p1;
            rs1 += p2 + p3;
            *(float2*)(Ps + (r0 + g)     * PST + nf * 8 + 2 * c) = make_float2(p0, p1);
            *(float2*)(Ps + (r0 + g + 8) * PST + nf * 8 + 2 * c) = make_float2(p2, p3);
        }
        rs0 += __shfl_xor_sync(0xffffffffu, rs0, 1);
        rs0 += __shfl_xor_sync(0xffffffffu, rs0, 2);
        rs1 += __shfl_xor_sync(0xffffffffu, rs1, 1);
        rs1 += __shfl_xor_sync(0xffffffffu, rs1, 2);
        lr0 = lr0 * corr0 + rs0;
        lr1 = lr1 * corr1 + rs1;

        // warp-uniform rescale skip (corr==1 for most tiles below diagonal)
        bool noresc = __all_sync(0xffffffffu, (corr0 == 1.0f) && (corr1 == 1.0f));
        if (!noresc) {
#pragma unroll
            for (int nf = 0; nf < 16; nf++) {
                o[nf].x *= corr0; o[nf].y *= corr0;
                o[nf].z *= corr1; o[nf].w *= corr1;
            }
        }

        // V(kt2) ready (only K prefetch may remain pending)
        asm volatile("cp.async.wait_group 1;\n");
        __syncthreads();

        // ---- O += P * Vhi (single pass), 16 x 128 per warp ----
#pragma unroll 2
        for (int kc = 0; kc < 8; kc++) {
            const int k0 = kc * 8;
            uint32_t ua[4];
            ua[0] = uPs[(r0 + g)     * PST + k0 + c];
            ua[1] = uPs[(r0 + g + 8) * PST + k0 + c];
            ua[2] = uPs[(r0 + g)     * PST + k0 + c + 4];
            ua[3] = uPs[(r0 + g + 8) * PST + k0 + c + 4];
#pragma unroll
            for (int nf = 0; nf < 16; nf++) {
                uint32_t bhi[2];
                bhi[0] = uVhi[(k0 + c)     * VST + nf * 8 + g];
                bhi[1] = uVhi[(k0 + c + 4) * VST + nf * 8 + g];
                mma_tf32(o[nf], ua, bhi);
            }
        }

        if (last) break;   // remaining tiles are beyond the ALiBi horizon
    }

    asm volatile("cp.async.wait_group 0;\n");  // drain any pending groups

    // ---- epilogue ----
    float inv0 = 1.f / lr0, inv1 = 1.f / lr1;
    int t0 = i0 + r0 + g, t1 = t0 + 8;
    float* d0 = g_att + ((size_t)b * TT + t0) * CC + h * DD;
    float* d1 = g_att + ((size_t)b * TT + t1) * CC + h * DD;
#pragma unroll
    for (int nf = 0; nf < 16; nf++) {
        int col = nf * 8 + 2 * c;
        *(float2*)(d0 + col) = make_float2(__uint_as_float(f2tf32(o[nf].x * inv0)),
                                           __uint_as_float(f2tf32(o[nf].y * inv0)));
        *(float2*)(d1 + col) = make_float2(__uint_as_float(f2tf32(o[nf].z * inv1)),
                                           __uint_as_float(f2tf32(o[nf].w * inv1)));
    }
}

// ---------------------------------------------------------------------------
extern "C" void kernel_launch(void* const* d_in, const int* in_sizes, int n_in,
                              void* d_out, int out_size) {
    (void)in_sizes; (void)n_in; (void)out_size;
    const float* x    = (const float*)d_in[0];
    const float* Wqkv = (const float*)d_in[3];
    const float* Wout = (const float*)d_in[4];
    float* out = (float*)d_out;

    rope_table_kernel<<<TT / 4, 256>>>();

    {
        int n4x = BB * TT * CC / 4;
        int n4q = 3 * CC * CC / 4;
        int n4o = CC * CC / 4;
        cvt_tf32_kernel<0><<<(n4x + 255) / 256, 256>>>(x, n4x);
        cvt_tf32_kernel<1><<<(n4q + 255) / 256, 256>>>(Wqkv, n4q);
        cvt_tf32_kernel<2><<<(n4o + 255) / 256, 256>>>(Wout, n4o);
    }

    dim3 g1(3 * CC / 128, BB * TT / 128);   // (48, 32)
    gemm_tf32<0><<<g1, 256>>>(nullptr);

    rope_split_kernel<<<3 * BB * HH * TT / 4, 256>>>();

    cudaFuncSetAttribute(attn_mma_kernel,
                         cudaFuncAttributeMaxDynamicSharedMemorySize, ATTN_SMEM);
    dim3 g2(TT / AM, BB * HH);              // (16, 32)
    attn_mma_kernel<<<g2, 256, ATTN_SMEM>>>();

    dim3 g3(CC / 128, BB * TT / 128);       // (16, 32)
    gemm_tf32<1><<<g3, 256>>>(out);
}